// round 9
// baseline (speedup 1.0000x reference)
#include <cuda_runtime.h>
#include <cuda_bf16.h>
#include <cstdint>
#include <math.h>

// ---------------- Problem constants ----------------
#define BB 2
#define LL 1024
#define DM 1024
#define DI 2048            // d_inner
#define DS 16              // d_state
#define DC 4               // d_conv
#define DR 64              // dt_rank
#define XZ_W (2*DI)        // 4096
#define XDBL_W (DR + 2*DS) // 96
#define MROWS (BB*LL)      // 2048
#define NSPLIT 8
#define KSPLIT 256         // 2048 / 8 for gemm_x

// ---------------- Scratch (device globals; no allocation allowed) ----------------
__device__ float g_xz   [MROWS*XZ_W];
__device__ float g_u    [MROWS*DI];
__device__ float g_xdbl [MROWS*XDBL_W];
__device__ float g_xpart[NSPLIT*MROWS*XDBL_W];
__device__ float g_opart[2*MROWS*DM];
__device__ float g_dt   [MROWS*DI];
__device__ __nv_bfloat16 g_xb   [MROWS*DM];
__device__ __nv_bfloat16 g_hb   [MROWS*DM];
__device__ __nv_bfloat16 g_ub   [MROWS*DI];
__device__ __nv_bfloat16 g_yb   [MROWS*DI];
__device__ __nv_bfloat16 g_xdblb[MROWS*XDBL_W];
__device__ __nv_bfloat16 g_Wib  [2*XZ_W*DM];
__device__ __nv_bfloat16 g_Wxb  [2*XDBL_W*DI];
__device__ __nv_bfloat16 g_Wdtb [2*DI*DR];
__device__ __nv_bfloat16 g_Wob  [2*DM*DI];

// ---------------- helpers ----------------
__device__ __forceinline__ uint32_t smem_u32(const void* p) {
    uint32_t a;
    asm("{ .reg .u64 t; cvta.to.shared.u64 t, %1; cvt.u32.u64 %0, t; }" : "=r"(a) : "l"(p));
    return a;
}
__device__ __forceinline__ void cp16(uint32_t s, const void* g) {
    asm volatile("cp.async.cg.shared.global [%0], [%1], 16;" :: "r"(s), "l"(g));
}
#define CP_COMMIT()  asm volatile("cp.async.commit_group;" ::: "memory")
#define CP_WAIT(n)   asm volatile("cp.async.wait_group %0;" :: "n"(n) : "memory")

__device__ __forceinline__ void ldsm4(uint32_t* r, uint32_t addr) {
    asm volatile("ldmatrix.sync.aligned.m8n8.x4.shared.b16 {%0,%1,%2,%3}, [%4];"
                 : "=r"(r[0]), "=r"(r[1]), "=r"(r[2]), "=r"(r[3]) : "r"(addr));
}
__device__ __forceinline__ void mma_bf16(float* c, const uint32_t* a, const uint32_t* b) {
    asm volatile(
        "mma.sync.aligned.m16n8k16.row.col.f32.bf16.bf16.f32 "
        "{%0,%1,%2,%3}, {%4,%5,%6,%7}, {%8,%9}, {%0,%1,%2,%3};"
        : "+f"(c[0]), "+f"(c[1]), "+f"(c[2]), "+f"(c[3])
        : "r"(a[0]), "r"(a[1]), "r"(a[2]), "r"(a[3]), "r"(b[0]), "r"(b[1]));
}

// ---------------- mma.sync bf16 NT GEMM ----------------
// C[m,n] = sum_k A[m*lda+k] * W[n*ldw+k]   (A, W bf16 K-major; ldw = W row stride)
// CTA tile (64*MI) x 128, BK=64, 3-stage cp.async, 8 warps.
// EPI: 0=fp32, 1=softplus(c+bias[n]) fp32, 2=c+res fp32, 3=bf16 only
// SPLIT: split-K over blockIdx.z; K = per-split k-length; k-offset bz*K applied
//        to BOTH A and W (within-row, strides lda/ldw); partial slice = bz*MROWS*ldc.
#define ELD 132

template <int MI, int EPI, bool SPLIT>
__global__ void __launch_bounds__(256, 2)
gemm_mma(const __nv_bfloat16* __restrict__ A, int lda,
         const __nv_bfloat16* __restrict__ W, int ldw,
         float* __restrict__ Cf, __nv_bfloat16* __restrict__ Cb,
         int N, int ldc, int K,
         const float* __restrict__ bias, const float* __restrict__ res)
{
    constexpr int BM = 64 * MI;
    constexpr int STAGE = BM * 128 + 16384;
    extern __shared__ __align__(16) char smem[];

    if (SPLIT) {
        int bz = blockIdx.z;
        A  += bz * K;                       // k-offset (row stride lda)
        W  += bz * K;                       // k-offset (row stride ldw)
        Cf += (size_t)bz * MROWS * ldc;     // partial slice
    }

    const int tid  = threadIdx.x;
    const int wid  = tid >> 5;
    const int lane = tid & 31;
    const int wm   = wid & 3;
    const int wn   = wid >> 2;
    const int bx   = blockIdx.x, by = blockIdx.y;
    const int bxN  = bx * 128;

    const uint32_t sbase = smem_u32(smem);
    const __nv_bfloat16* Ap = A + (size_t)(by * BM) * lda;
    const __nv_bfloat16* Wp = W + (size_t)bxN * ldw;

    const int nk = K >> 6;

    auto load_stage = [&](int kt) {
        const int st = kt % 3;
        const int k0 = kt * 64;
        uint32_t sa = sbase + st * STAGE;
        uint32_t sb = sa + BM * 128;
#pragma unroll
        for (int j = 0; j < 2 * MI; ++j) {
            int c = tid + 256 * j;
            int row = c >> 3, ch = c & 7;
            uint32_t off = row * 128 + ((ch ^ (row & 7)) << 4);
            cp16(sa + off, Ap + (size_t)row * lda + k0 + ch * 8);
        }
#pragma unroll
        for (int j = 0; j < 4; ++j) {
            int c = tid + 256 * j;
            int row = c >> 3, ch = c & 7;
            uint32_t off = row * 128 + ((ch ^ (row & 7)) << 4);
            if (bxN + row < N)
                cp16(sb + off, Wp + (size_t)row * ldw + k0 + ch * 8);
        }
        CP_COMMIT();
    };

    float acc[MI][8][4];
#pragma unroll
    for (int i = 0; i < MI; ++i)
#pragma unroll
        for (int j = 0; j < 8; ++j)
#pragma unroll
            for (int c = 0; c < 4; ++c) acc[i][j][c] = 0.f;

    const int a_rl  = lane & 15;
    const int a_kc  = lane >> 4;
    const int a_xor = lane & 7;
    const int b_nl  = (lane & 7) + ((lane >> 4) << 3);
    const int b_kc  = (lane >> 3) & 1;

    load_stage(0);
    if (nk > 1) load_stage(1); else CP_COMMIT();

    for (int kt = 0; kt < nk; ++kt) {
        CP_WAIT(1);
        __syncthreads();
        if (kt + 2 < nk) load_stage(kt + 2); else CP_COMMIT();

        const uint32_t sa = sbase + (kt % 3) * STAGE;
        const uint32_t sb = sa + BM * 128;

#pragma unroll
        for (int ks = 0; ks < 4; ++ks) {
            uint32_t af[MI][4];
            uint32_t aoff = (uint32_t)(((ks * 2 + a_kc) ^ a_xor) << 4);
#pragma unroll
            for (int mi = 0; mi < MI; ++mi)
                ldsm4(af[mi], sa + (wm * (16 * MI) + mi * 16 + a_rl) * 128 + aoff);
#pragma unroll
            for (int nj = 0; nj < 4; ++nj) {
                uint32_t bf[4];
                int nl = wn * 64 + nj * 16 + b_nl;
                uint32_t boff = nl * 128 + (((ks * 2 + b_kc) ^ (b_nl & 7)) << 4);
                ldsm4(bf, sb + boff);
#pragma unroll
                for (int mi = 0; mi < MI; ++mi) {
                    mma_bf16(acc[mi][nj * 2 + 0], af[mi], bf + 0);
                    mma_bf16(acc[mi][nj * 2 + 1], af[mi], bf + 2);
                }
            }
        }
    }
    __syncthreads();

    // ---------------- single-pass epilogue ----------------
    float* sEpi = (float*)smem;
#pragma unroll
    for (int mi = 0; mi < MI; ++mi)
#pragma unroll
        for (int nt = 0; nt < 8; ++nt) {
            int r  = wm * (16 * MI) + mi * 16 + (lane >> 2);
            int cc = wn * 64 + nt * 8 + (lane & 3) * 2;
            *(float2*)&sEpi[r * ELD + cc]       = make_float2(acc[mi][nt][0], acc[mi][nt][1]);
            *(float2*)&sEpi[(r + 8) * ELD + cc] = make_float2(acc[mi][nt][2], acc[mi][nt][3]);
        }
    __syncthreads();

    {
        int nn = tid & 127, r0 = tid >> 7;
        int n = bxN + nn;
        if (n < N) {
            float bv = (EPI == 1) ? bias[n] : 0.f;
#pragma unroll 4
            for (int rr = r0; rr < BM; rr += 2) {
                int m = by * BM + rr;
                float v = sEpi[rr * ELD + nn];
                if (EPI == 1) {
                    float t = v + bv;
                    v = (t > 20.f) ? t : log1pf(__expf(t));
                    Cf[(size_t)m * ldc + n] = v;
                } else if (EPI == 2) {
                    Cf[(size_t)m * ldc + n] = v + res[(size_t)m * ldc + n];
                } else if (EPI == 3) {
                    Cb[(size_t)m * ldc + n] = __float2bfloat16(v);
                } else {
                    Cf[(size_t)m * ldc + n] = v;
                }
            }
        }
    }
}

// ---------------- split-K reduce: xdbl = sum_z xpart[z], + bf16 copy ----------------
__global__ void reduce_x_kernel(const float* __restrict__ part,
                                float* __restrict__ xdbl,
                                __nv_bfloat16* __restrict__ xdblb)
{
    int i = blockIdx.x * blockDim.x + threadIdx.x;
    if (i >= MROWS * XDBL_W) return;
    float s = 0.f;
#pragma unroll
    for (int z = 0; z < NSPLIT; ++z)
        s += part[(size_t)z * MROWS * XDBL_W + i];
    xdbl[i]  = s;
    xdblb[i] = __float2bfloat16(s);
}

// ---------------- split-K reduce for out-GEMM (2 partials) ----------------
// RES=false: write bf16 to outb.  RES=true: write fp32 out + residual x.
template <bool RES>
__global__ void reduce_out_kernel(const float* __restrict__ part,
                                  const float* __restrict__ x,
                                  float* __restrict__ outf,
                                  __nv_bfloat16* __restrict__ outb)
{
    int i = (blockIdx.x * blockDim.x + threadIdx.x) * 4;
    if (i >= MROWS * DM) return;
    float4 a = *(const float4*)(part + i);
    float4 b = *(const float4*)(part + MROWS * DM + i);
    float4 s = make_float4(a.x + b.x, a.y + b.y, a.z + b.z, a.w + b.w);
    if (RES) {
        float4 r = *(const float4*)(x + i);
        s.x += r.x; s.y += r.y; s.z += r.z; s.w += r.w;
        *(float4*)(outf + i) = s;
    } else {
        __nv_bfloat162 o0 = __floats2bfloat162_rn(s.x, s.y);
        __nv_bfloat162 o1 = __floats2bfloat162_rn(s.z, s.w);
        uint32_t u0 = *(uint32_t*)&o0, u1 = *(uint32_t*)&o1;
        uint2 o; o.x = u0; o.y = u1;
        *(uint2*)(outb + i) = o;
    }
}

// ---------------- fused fp32 -> bf16 convert for x + all weights ----------------
#define CVT_N0 (MROWS*DM)
#define CVT_N1 (2*XZ_W*DM)
#define CVT_N2 (2*XDBL_W*DI)
#define CVT_N3 (2*DI*DR)
#define CVT_N4 (2*DM*DI)
#define CVT_TOT (CVT_N0+CVT_N1+CVT_N2+CVT_N3+CVT_N4)

__global__ void cvt_all_kernel(const float* __restrict__ x,  __nv_bfloat16* __restrict__ xb,
                               const float* __restrict__ w1, __nv_bfloat16* __restrict__ d1,
                               const float* __restrict__ w2, __nv_bfloat16* __restrict__ d2,
                               const float* __restrict__ w3, __nv_bfloat16* __restrict__ d3,
                               const float* __restrict__ w4, __nv_bfloat16* __restrict__ d4)
{
    int i = (blockIdx.x * blockDim.x + threadIdx.x) * 8;
    if (i >= CVT_TOT) return;
    const float* s; __nv_bfloat16* d;
    if      (i < CVT_N0)                          { s = x;  d = xb; }
    else if (i < CVT_N0+CVT_N1)                   { s = w1 - CVT_N0; d = d1 - CVT_N0; }
    else if (i < CVT_N0+CVT_N1+CVT_N2)            { s = w2 - CVT_N0-CVT_N1; d = d2 - CVT_N0-CVT_N1; }
    else if (i < CVT_N0+CVT_N1+CVT_N2+CVT_N3)     { s = w3 - CVT_N0-CVT_N1-CVT_N2; d = d3 - CVT_N0-CVT_N1-CVT_N2; }
    else                                          { s = w4 - CVT_N0-CVT_N1-CVT_N2-CVT_N3; d = d4 - CVT_N0-CVT_N1-CVT_N2-CVT_N3; }
    float4 v0 = *(const float4*)(s + i);
    float4 v1 = *(const float4*)(s + i + 4);
    __nv_bfloat162 b0 = __floats2bfloat162_rn(v0.x, v0.y);
    __nv_bfloat162 b1 = __floats2bfloat162_rn(v0.z, v0.w);
    __nv_bfloat162 b2 = __floats2bfloat162_rn(v1.x, v1.y);
    __nv_bfloat162 b3 = __floats2bfloat162_rn(v1.z, v1.w);
    uint4 o;
    o.x = *(uint32_t*)&b0; o.y = *(uint32_t*)&b1;
    o.z = *(uint32_t*)&b2; o.w = *(uint32_t*)&b3;
    *(uint4*)(d + i) = o;
}

// ---------------- Depthwise causal conv1d (width 4) + bias + SiLU ----------------
__global__ void conv_silu_kernel(const float* __restrict__ xz,
                                 const float* __restrict__ cw,
                                 const float* __restrict__ cb,
                                 float* __restrict__ u,
                                 __nv_bfloat16* __restrict__ ub)
{
    int idx = blockIdx.x * blockDim.x + threadIdx.x;
    if (idx >= BB * LL * DI) return;
    int d  = idx & (DI - 1);
    int bl = idx >> 11;
    int l  = bl & (LL - 1);
    int b  = bl >> 10;

    float w0 = cw[d * 4 + 0], w1 = cw[d * 4 + 1];
    float w2 = cw[d * 4 + 2], w3 = cw[d * 4 + 3];
    float acc = cb[d];
    const float* base = xz + ((size_t)b * LL) * XZ_W + d;
    if (l - 3 >= 0) acc += base[(size_t)(l - 3) * XZ_W] * w0;
    if (l - 2 >= 0) acc += base[(size_t)(l - 2) * XZ_W] * w1;
    if (l - 1 >= 0) acc += base[(size_t)(l - 1) * XZ_W] * w2;
    acc += base[(size_t)l * XZ_W] * w3;
    float s = acc / (1.f + __expf(-acc));
    u[idx]  = s;
    ub[idx] = __float2bfloat16(s);
}

// ---------------- Selective scan v2 (cp.async SMEM-staged) ----------------
// 256 blocks (16 d-rows each), 128 threads: 8 lanes per d-row, 2 states/lane.
// Per 64-step chunk stage dt/u/z (64x16) and B/C (64x16) f32, double-buffered.
#define SST 5120                 // floats per stage (5 tiles x 1024)
#define SCAN_SMEM (2*SST*4)      // 40960 B

__global__ void __launch_bounds__(128, 2)
scan_kernel(const float* __restrict__ dt,
            const float* __restrict__ u,
            const float* __restrict__ xdbl,
            const float* __restrict__ A_log,
            const float* __restrict__ Dvec,
            const float* __restrict__ xz,
            __nv_bfloat16* __restrict__ yb)
{
    extern __shared__ __align__(16) float S[];
    const uint32_t sbase = smem_u32(S);

    const int tid = threadIdx.x;
    const int q   = tid & 7;         // state pair: states q*2, q*2+1
    const int dl  = tid >> 3;        // local row 0..15
    const int b   = blockIdx.x >> 7; // 128 groups per batch
    const int d0  = (blockIdx.x & 127) << 4;
    const int d   = d0 + dl;

    const float Av0 = -__expf(A_log[(size_t)d * DS + q * 2 + 0]);
    const float Av1 = -__expf(A_log[(size_t)d * DS + q * 2 + 1]);
    const float Dv  = Dvec[d];

    auto load_chunk = [&](int c, int stg) {
        const size_t grow = (size_t)b * LL + c * 64;
        uint32_t s0 = sbase + stg * SST * 4;
        // all five 64x16 f32 tiles share one index map: 256 cp16 each, 2/thread
#pragma unroll
        for (int j = 0; j < 2; ++j) {
            int idx = tid + 128 * j;       // 0..255
            int tt = idx >> 2, ch = idx & 3;
            uint32_t doff = (tt * 16 + ch * 4) * 4;
            size_t gr = (grow + tt);
            cp16(s0 + doff,            dt   + gr * DI + d0 + ch * 4);
            cp16(s0 + 4096  + doff,    u    + gr * DI + d0 + ch * 4);
            cp16(s0 + 8192  + doff,    xz   + gr * XZ_W + DI + d0 + ch * 4);
            cp16(s0 + 12288 + doff,    xdbl + gr * XDBL_W + DR + ch * 4);
            cp16(s0 + 16384 + doff,    xdbl + gr * XDBL_W + DR + DS + ch * 4);
        }
        CP_COMMIT();
    };

    float h0 = 0.f, h1 = 0.f;
    const int nchunks = LL / 64;   // 16

    load_chunk(0, 0);

    for (int c = 0; c < nchunks; ++c) {
        if (c + 1 < nchunks) { load_chunk(c + 1, (c + 1) & 1); CP_WAIT(1); }
        else                 { CP_WAIT(0); }
        __syncthreads();

        const float* sd = S + (c & 1) * SST;
        const int t0 = c * 64;

#pragma unroll 4
        for (int tt = 0; tt < 64; ++tt) {
            float dtv = sd[tt * 16 + dl];
            float uv  = sd[1024 + tt * 16 + dl];
            float dtu = dtv * uv;

            float dA0 = __expf(dtv * Av0);
            float dA1 = __expf(dtv * Av1);
            float2 Bv = *(const float2*)&sd[3072 + tt * 16 + q * 2];
            float2 Cv = *(const float2*)&sd[4096 + tt * 16 + q * 2];
            h0 = dA0 * h0 + dtu * Bv.x;
            h1 = dA1 * h1 + dtu * Bv.y;
            float ys = h0 * Cv.x + h1 * Cv.y;

            ys += __shfl_xor_sync(0xffffffff, ys, 1);
            ys += __shfl_xor_sync(0xffffffff, ys, 2);
            ys += __shfl_xor_sync(0xffffffff, ys, 4);

            if (q == 0) {
                float zv = sd[2048 + tt * 16 + dl];
                float sz = zv / (1.f + __expf(-zv));
                yb[((size_t)b * LL + t0 + tt) * DI + d] =
                    __float2bfloat16((ys + uv * Dv) * sz);
            }
        }
        __syncthreads();
    }
}

// ---------------- Host launcher ----------------
extern "C" void kernel_launch(void* const* d_in, const int* in_sizes, int n_in,
                              void* d_out, int out_size)
{
    const float* x      = (const float*)d_in[0];
    const float* W_in   = (const float*)d_in[1];
    const float* conv_w = (const float*)d_in[2];
    const float* conv_b = (const float*)d_in[3];
    const float* W_x    = (const float*)d_in[4];
    const float* W_dt   = (const float*)d_in[5];
    const float* b_dt   = (const float*)d_in[6];
    const float* A_log  = (const float*)d_in[7];
    const float* Dvec   = (const float*)d_in[8];
    const float* W_out  = (const float*)d_in[9];
    float* out = (float*)d_out;

    float *xz, *u, *xdbl, *xpart, *opart, *dt;
    __nv_bfloat16 *xb, *hb, *ub, *yb, *xdblb, *Wib, *Wxb, *Wdtb, *Wob;
    cudaGetSymbolAddress((void**)&xz,    g_xz);
    cudaGetSymbolAddress((void**)&u,     g_u);
    cudaGetSymbolAddress((void**)&xdbl,  g_xdbl);
    cudaGetSymbolAddress((void**)&xpart, g_xpart);
    cudaGetSymbolAddress((void**)&opart, g_opart);
    cudaGetSymbolAddress((void**)&dt,    g_dt);
    cudaGetSymbolAddress((void**)&xb,    g_xb);
    cudaGetSymbolAddress((void**)&hb,    g_hb);
    cudaGetSymbolAddress((void**)&ub,    g_ub);
    cudaGetSymbolAddress((void**)&yb,    g_yb);
    cudaGetSymbolAddress((void**)&xdblb, g_xdblb);
    cudaGetSymbolAddress((void**)&Wib,   g_Wib);
    cudaGetSymbolAddress((void**)&Wxb,   g_Wxb);
    cudaGetSymbolAddress((void**)&Wdtb,  g_Wdtb);
    cudaGetSymbolAddress((void**)&Wob,   g_Wob);

    const int SMEM_MI2 = 3 * (128 * 128 + 16384);   // 98304
    const int SMEM_MI1 = 3 * (64 * 128 + 16384);    // 73728
    cudaFuncSetAttribute(gemm_mma<2,0,false>, cudaFuncAttributeMaxDynamicSharedMemorySize, SMEM_MI2);
    cudaFuncSetAttribute(gemm_mma<2,0,true>,  cudaFuncAttributeMaxDynamicSharedMemorySize, SMEM_MI2);
    cudaFuncSetAttribute(gemm_mma<1,1,false>, cudaFuncAttributeMaxDynamicSharedMemorySize, SMEM_MI1);
    cudaFuncSetAttribute(scan_kernel, cudaFuncAttributeMaxDynamicSharedMemorySize, SCAN_SMEM);

    // #1: all fp32->bf16 converts, fused
    cvt_all_kernel<<<(CVT_TOT / 8 + 255) / 256, 256>>>(
        x, xb, W_in, Wib, W_x, Wxb, W_dt, Wdtb, W_out, Wob);

    for (int layer = 0; layer < 2; ++layer) {
        const __nv_bfloat16* in_b   = (layer == 0) ? xb : hb;
        const __nv_bfloat16* Wib_l  = Wib  + (size_t)layer * XZ_W * DM;
        const __nv_bfloat16* Wxb_l  = Wxb  + (size_t)layer * XDBL_W * DI;
        const __nv_bfloat16* Wdtb_l = Wdtb + (size_t)layer * DI * DR;
        const __nv_bfloat16* Wob_l  = Wob  + (size_t)layer * DM * DI;
        const float* conv_w_l = conv_w + (size_t)layer * DI * DC;
        const float* conv_b_l = conv_b + (size_t)layer * DI;
        const float* b_dt_l   = b_dt   + (size_t)layer * DI;
        const float* A_log_l  = A_log  + (size_t)layer * DI * DS;
        const float* D_l      = Dvec   + (size_t)layer * DI;

        // #2: xz = in @ W_in^T : M=2048, N=4096, K=1024  (512 CTAs)
        gemm_mma<2,0,false><<<dim3(XZ_W / 128, MROWS / 128), 256, SMEM_MI2>>>(
            in_b, DM, Wib_l, DM, xz, nullptr, XZ_W, XZ_W, DM, nullptr, nullptr);

        // #3: u = silu(causal_conv(xz[:, :DI]))
        conv_silu_kernel<<<(BB * LL * DI) / 256, 256>>>(xz, conv_w_l, conv_b_l, u, ub);

        // #4 (profiled): x_dbl partials = u @ W_x^T split-K x8 (ldw = DI, FIXED)
        gemm_mma<2,0,true><<<dim3(1, MROWS / 128, NSPLIT), 256, SMEM_MI2>>>(
            ub, DI, Wxb_l, DI, xpart, nullptr, XDBL_W, XDBL_W, KSPLIT, nullptr, nullptr);

        // #5: reduce partials -> xdbl fp32 + bf16
        reduce_x_kernel<<<(MROWS * XDBL_W + 255) / 256, 256>>>(xpart, xdbl, xdblb);

        // #6: dt = softplus(x_dbl[:, :64] @ W_dt^T + b_dt) : N=2048, K=64 (512 CTAs)
        gemm_mma<1,1,false><<<dim3(DI / 128, MROWS / 64), 256, SMEM_MI1>>>(
            xdblb, XDBL_W, Wdtb_l, DR, dt, nullptr, DI, DI, DR, b_dt_l, nullptr);

        // #7: selective scan v2 (256 CTAs)
        scan_kernel<<<BB * (DI / 16), 128, SCAN_SMEM>>>(
            dt, u, xdbl, A_log_l, D_l, xz, yb);

        // #8: out partials = y @ W_out^T split-K x2 : 256 CTAs
        gemm_mma<2,0,true><<<dim3(DM / 128, MROWS / 128, 2), 256, SMEM_MI2>>>(
            yb, DI, Wob_l, DI, opart, nullptr, DM, DM, DI / 2, nullptr, nullptr);

        // #9: reduce out partials (+ residual on last layer)
        if (layer == 0) {
            reduce_out_kernel<false><<<(MROWS * DM / 4 + 255) / 256, 256>>>(
                opart, nullptr, nullptr, hb);
        } else {
            reduce_out_kernel<true><<<(MROWS * DM / 4 + 255) / 256, 256>>>(
                opart, x, out, nullptr);
        }
    }
}

// round 10
// speedup vs baseline: 1.0686x; 1.0686x over previous
#include <cuda_runtime.h>
#include <cuda_bf16.h>
#include <cstdint>
#include <math.h>

// ---------------- Problem constants ----------------
#define BB 2
#define LL 1024
#define DM 1024
#define DI 2048            // d_inner
#define DS 16              // d_state
#define DC 4               // d_conv
#define DR 64              // dt_rank
#define XZ_W (2*DI)        // 4096
#define XDBL_W (DR + 2*DS) // 96
#define MROWS (BB*LL)      // 2048
#define NSPLIT 8
#define KSPLIT 256         // 2048 / 8 for gemm_x

// ---------------- Scratch (device globals; no allocation allowed) ----------------
__device__ float g_xdbl [MROWS*XDBL_W];          // fp32 for scan B/C
__device__ float g_xpart[NSPLIT*MROWS*XDBL_W];
__device__ __nv_bfloat16 g_xzb  [MROWS*XZ_W];
__device__ __nv_bfloat16 g_dtb  [MROWS*DI];
__device__ __nv_bfloat16 g_xb   [MROWS*DM];
__device__ __nv_bfloat16 g_hb   [MROWS*DM];
__device__ __nv_bfloat16 g_ub   [MROWS*DI];
__device__ __nv_bfloat16 g_yb   [MROWS*DI];
__device__ __nv_bfloat16 g_xdblb[MROWS*XDBL_W];
__device__ __nv_bfloat16 g_Wib  [2*XZ_W*DM];
__device__ __nv_bfloat16 g_Wxb  [2*XDBL_W*DI];
__device__ __nv_bfloat16 g_Wdtb [2*DI*DR];
__device__ __nv_bfloat16 g_Wob  [2*DM*DI];

// ---------------- helpers ----------------
__device__ __forceinline__ uint32_t smem_u32(const void* p) {
    uint32_t a;
    asm("{ .reg .u64 t; cvta.to.shared.u64 t, %1; cvt.u32.u64 %0, t; }" : "=r"(a) : "l"(p));
    return a;
}
__device__ __forceinline__ void cp16(uint32_t s, const void* g) {
    asm volatile("cp.async.cg.shared.global [%0], [%1], 16;" :: "r"(s), "l"(g));
}
#define CP_COMMIT()  asm volatile("cp.async.commit_group;" ::: "memory")
#define CP_WAIT(n)   asm volatile("cp.async.wait_group %0;" :: "n"(n) : "memory")

__device__ __forceinline__ void ldsm4(uint32_t* r, uint32_t addr) {
    asm volatile("ldmatrix.sync.aligned.m8n8.x4.shared.b16 {%0,%1,%2,%3}, [%4];"
                 : "=r"(r[0]), "=r"(r[1]), "=r"(r[2]), "=r"(r[3]) : "r"(addr));
}
__device__ __forceinline__ void mma_bf16(float* c, const uint32_t* a, const uint32_t* b) {
    asm volatile(
        "mma.sync.aligned.m16n8k16.row.col.f32.bf16.bf16.f32 "
        "{%0,%1,%2,%3}, {%4,%5,%6,%7}, {%8,%9}, {%0,%1,%2,%3};"
        : "+f"(c[0]), "+f"(c[1]), "+f"(c[2]), "+f"(c[3])
        : "r"(a[0]), "r"(a[1]), "r"(a[2]), "r"(a[3]), "r"(b[0]), "r"(b[1]));
}

// ---------------- mma.sync bf16 NT GEMM ----------------
// C[m,n] = sum_k A[m*lda+k] * W[n*ldw+k]
// EPI: 0 = fp32 Cf, 1 = softplus(c+bias[n]) -> bf16 Cb,
//      2 = c+res -> fp32 Cf, 3 = bf16 Cb
// SPLIT: split-K over blockIdx.z; K = per-split length; k-offset bz*K on A and W.
#define ELD 132

template <int MI, int EPI, bool SPLIT>
__global__ void __launch_bounds__(256, 2)
gemm_mma(const __nv_bfloat16* __restrict__ A, int lda,
         const __nv_bfloat16* __restrict__ W, int ldw,
         float* __restrict__ Cf, __nv_bfloat16* __restrict__ Cb,
         int N, int ldc, int K,
         const float* __restrict__ bias, const float* __restrict__ res)
{
    constexpr int BM = 64 * MI;
    constexpr int STAGE = BM * 128 + 16384;
    extern __shared__ __align__(16) char smem[];

    if (SPLIT) {
        int bz = blockIdx.z;
        A  += bz * K;
        W  += bz * K;
        Cf += (size_t)bz * MROWS * ldc;
    }

    const int tid  = threadIdx.x;
    const int wid  = tid >> 5;
    const int lane = tid & 31;
    const int wm   = wid & 3;
    const int wn   = wid >> 2;
    const int bx   = blockIdx.x, by = blockIdx.y;
    const int bxN  = bx * 128;

    const uint32_t sbase = smem_u32(smem);
    const __nv_bfloat16* Ap = A + (size_t)(by * BM) * lda;
    const __nv_bfloat16* Wp = W + (size_t)bxN * ldw;

    const int nk = K >> 6;

    auto load_stage = [&](int kt) {
        const int st = kt % 3;
        const int k0 = kt * 64;
        uint32_t sa = sbase + st * STAGE;
        uint32_t sb = sa + BM * 128;
#pragma unroll
        for (int j = 0; j < 2 * MI; ++j) {
            int c = tid + 256 * j;
            int row = c >> 3, ch = c & 7;
            uint32_t off = row * 128 + ((ch ^ (row & 7)) << 4);
            cp16(sa + off, Ap + (size_t)row * lda + k0 + ch * 8);
        }
#pragma unroll
        for (int j = 0; j < 4; ++j) {
            int c = tid + 256 * j;
            int row = c >> 3, ch = c & 7;
            uint32_t off = row * 128 + ((ch ^ (row & 7)) << 4);
            if (bxN + row < N)
                cp16(sb + off, Wp + (size_t)row * ldw + k0 + ch * 8);
        }
        CP_COMMIT();
    };

    float acc[MI][8][4];
#pragma unroll
    for (int i = 0; i < MI; ++i)
#pragma unroll
        for (int j = 0; j < 8; ++j)
#pragma unroll
            for (int c = 0; c < 4; ++c) acc[i][j][c] = 0.f;

    const int a_rl  = lane & 15;
    const int a_kc  = lane >> 4;
    const int a_xor = lane & 7;
    const int b_nl  = (lane & 7) + ((lane >> 4) << 3);
    const int b_kc  = (lane >> 3) & 1;

    load_stage(0);
    if (nk > 1) load_stage(1); else CP_COMMIT();

    for (int kt = 0; kt < nk; ++kt) {
        CP_WAIT(1);
        __syncthreads();
        if (kt + 2 < nk) load_stage(kt + 2); else CP_COMMIT();

        const uint32_t sa = sbase + (kt % 3) * STAGE;
        const uint32_t sb = sa + BM * 128;

#pragma unroll
        for (int ks = 0; ks < 4; ++ks) {
            uint32_t af[MI][4];
            uint32_t aoff = (uint32_t)(((ks * 2 + a_kc) ^ a_xor) << 4);
#pragma unroll
            for (int mi = 0; mi < MI; ++mi)
                ldsm4(af[mi], sa + (wm * (16 * MI) + mi * 16 + a_rl) * 128 + aoff);
#pragma unroll
            for (int nj = 0; nj < 4; ++nj) {
                uint32_t bf[4];
                int nl = wn * 64 + nj * 16 + b_nl;
                uint32_t boff = nl * 128 + (((ks * 2 + b_kc) ^ (b_nl & 7)) << 4);
                ldsm4(bf, sb + boff);
#pragma unroll
                for (int mi = 0; mi < MI; ++mi) {
                    mma_bf16(acc[mi][nj * 2 + 0], af[mi], bf + 0);
                    mma_bf16(acc[mi][nj * 2 + 1], af[mi], bf + 2);
                }
            }
        }
    }
    __syncthreads();

    // ---------------- single-pass epilogue ----------------
    float* sEpi = (float*)smem;
#pragma unroll
    for (int mi = 0; mi < MI; ++mi)
#pragma unroll
        for (int nt = 0; nt < 8; ++nt) {
            int r  = wm * (16 * MI) + mi * 16 + (lane >> 2);
            int cc = wn * 64 + nt * 8 + (lane & 3) * 2;
            *(float2*)&sEpi[r * ELD + cc]       = make_float2(acc[mi][nt][0], acc[mi][nt][1]);
            *(float2*)&sEpi[(r + 8) * ELD + cc] = make_float2(acc[mi][nt][2], acc[mi][nt][3]);
        }
    __syncthreads();

    {
        int nn = tid & 127, r0 = tid >> 7;
        int n = bxN + nn;
        if (n < N) {
            float bv = (EPI == 1) ? bias[n] : 0.f;
#pragma unroll 4
            for (int rr = r0; rr < BM; rr += 2) {
                int m = by * BM + rr;
                float v = sEpi[rr * ELD + nn];
                if (EPI == 1) {
                    float t = v + bv;
                    v = (t > 20.f) ? t : log1pf(__expf(t));
                    Cb[(size_t)m * ldc + n] = __float2bfloat16(v);
                } else if (EPI == 2) {
                    Cf[(size_t)m * ldc + n] = v + res[(size_t)m * ldc + n];
                } else if (EPI == 3) {
                    Cb[(size_t)m * ldc + n] = __float2bfloat16(v);
                } else {
                    Cf[(size_t)m * ldc + n] = v;
                }
            }
        }
    }
}

// ---------------- split-K reduce: xdbl fp32 + bf16 ----------------
__global__ void reduce_x_kernel(const float* __restrict__ part,
                                float* __restrict__ xdbl,
                                __nv_bfloat16* __restrict__ xdblb)
{
    int i = blockIdx.x * blockDim.x + threadIdx.x;
    if (i >= MROWS * XDBL_W) return;
    float s = 0.f;
#pragma unroll
    for (int z = 0; z < NSPLIT; ++z)
        s += part[(size_t)z * MROWS * XDBL_W + i];
    xdbl[i]  = s;
    xdblb[i] = __float2bfloat16(s);
}

// ---------------- fp32 -> bf16 converts (two kernels, 2 and 3 tensors) ----------------
__global__ void cvt2_kernel(const float* __restrict__ s1, __nv_bfloat16* __restrict__ d1, int n1,
                            const float* __restrict__ s2, __nv_bfloat16* __restrict__ d2, int n2)
{
    int i = (blockIdx.x * blockDim.x + threadIdx.x) * 8;
    if (i >= n1 + n2) return;
    const float* s; __nv_bfloat16* d;
    if (i < n1) { s = s1; d = d1; }
    else        { s = s2 - n1; d = d2 - n1; }
    float4 v0 = *(const float4*)(s + i);
    float4 v1 = *(const float4*)(s + i + 4);
    __nv_bfloat162 b0 = __floats2bfloat162_rn(v0.x, v0.y);
    __nv_bfloat162 b1 = __floats2bfloat162_rn(v0.z, v0.w);
    __nv_bfloat162 b2 = __floats2bfloat162_rn(v1.x, v1.y);
    __nv_bfloat162 b3 = __floats2bfloat162_rn(v1.z, v1.w);
    uint4 o;
    o.x = *(uint32_t*)&b0; o.y = *(uint32_t*)&b1;
    o.z = *(uint32_t*)&b2; o.w = *(uint32_t*)&b3;
    *(uint4*)(d + i) = o;
}

__global__ void cvt3_kernel(const float* __restrict__ s1, __nv_bfloat16* __restrict__ d1, int n1,
                            const float* __restrict__ s2, __nv_bfloat16* __restrict__ d2, int n2,
                            const float* __restrict__ s3, __nv_bfloat16* __restrict__ d3, int n3)
{
    int i = (blockIdx.x * blockDim.x + threadIdx.x) * 8;
    if (i >= n1 + n2 + n3) return;
    const float* s; __nv_bfloat16* d;
    if      (i < n1)      { s = s1; d = d1; }
    else if (i < n1 + n2) { s = s2 - n1; d = d2 - n1; }
    else                  { s = s3 - n1 - n2; d = d3 - n1 - n2; }
    float4 v0 = *(const float4*)(s + i);
    float4 v1 = *(const float4*)(s + i + 4);
    __nv_bfloat162 b0 = __floats2bfloat162_rn(v0.x, v0.y);
    __nv_bfloat162 b1 = __floats2bfloat162_rn(v0.z, v0.w);
    __nv_bfloat162 b2 = __floats2bfloat162_rn(v1.x, v1.y);
    __nv_bfloat162 b3 = __floats2bfloat162_rn(v1.z, v1.w);
    uint4 o;
    o.x = *(uint32_t*)&b0; o.y = *(uint32_t*)&b1;
    o.z = *(uint32_t*)&b2; o.w = *(uint32_t*)&b3;
    *(uint4*)(d + i) = o;
}

// ---------------- Depthwise causal conv1d + bias + SiLU (bf16 in/out) ----------------
// 4 consecutive l per thread: 7 loads -> 4 outputs.
__global__ void conv_silu_kernel(const __nv_bfloat16* __restrict__ xzb,
                                 const float* __restrict__ cw,
                                 const float* __restrict__ cb,
                                 __nv_bfloat16* __restrict__ ub)
{
    int idx = blockIdx.x * blockDim.x + threadIdx.x;   // over B*(L/4)*DI
    if (idx >= BB * (LL / 4) * DI) return;
    int d  = idx & (DI - 1);
    int r  = idx >> 11;
    int l4 = r & (LL / 4 - 1);
    int b  = r >> 8;
    int l  = l4 * 4;

    float w0 = cw[d * 4 + 0], w1 = cw[d * 4 + 1];
    float w2 = cw[d * 4 + 2], w3 = cw[d * 4 + 3];
    float bv = cb[d];

    const __nv_bfloat16* base = xzb + ((size_t)b * LL) * XZ_W + d;
    float v[7];
#pragma unroll
    for (int i = 0; i < 3; ++i)
        v[i] = (l - 3 + i >= 0) ? __bfloat162float(base[(size_t)(l - 3 + i) * XZ_W]) : 0.f;
#pragma unroll
    for (int i = 3; i < 7; ++i)
        v[i] = __bfloat162float(base[(size_t)(l - 3 + i) * XZ_W]);

    __nv_bfloat16* ob = ub + ((size_t)b * LL + l) * DI + d;
#pragma unroll
    for (int o = 0; o < 4; ++o) {
        float acc = bv + v[o] * w0 + v[o + 1] * w1 + v[o + 2] * w2 + v[o + 3] * w3;
        float s = acc / (1.f + __expf(-acc));
        ob[(size_t)o * DI] = __float2bfloat16(s);
    }
}

// ---------------- Selective scan (cp.async SMEM-staged, bf16 dt/u/z, fp32 B/C) ----------------
// 128 blocks (32 d-rows each), 128 threads: 4 lanes per d-row, 4 states/lane.
// Stage layout (bytes): dt 0, u 4096, z 8192 (bf16 64x32 each); B 12288, C 16384 (f32 64x16).
#define SSTB 20480               // stage bytes
#define SCAN_SMEM (2*SSTB)       // 40960

__global__ void __launch_bounds__(128, 2)
scan_kernel(const __nv_bfloat16* __restrict__ dtb,
            const __nv_bfloat16* __restrict__ ub,
            const float* __restrict__ xdbl,
            const float* __restrict__ A_log,
            const float* __restrict__ Dvec,
            const __nv_bfloat16* __restrict__ xzb,
            __nv_bfloat16* __restrict__ yb)
{
    extern __shared__ __align__(16) char S[];
    const uint32_t sbase = smem_u32(S);

    const int tid = threadIdx.x;
    const int q   = tid & 3;
    const int dl  = tid >> 2;
    const int b   = blockIdx.x >> 6;
    const int d0  = (blockIdx.x & 63) << 5;
    const int d   = d0 + dl;

    float Av[4];
#pragma unroll
    for (int i = 0; i < 4; ++i)
        Av[i] = -__expf(A_log[(size_t)d * DS + q * 4 + i]);
    const float Dv = Dvec[d];

    auto load_chunk = [&](int c, int stg) {
        const size_t grow = (size_t)b * LL + c * 64;
        uint32_t s0 = sbase + stg * SSTB;
        // dt/u/z: 64 rows x 32 bf16 = 4 cp16/row, 256 per tile -> 2 per thread each
#pragma unroll
        for (int j = 0; j < 2; ++j) {
            int idx = tid + 128 * j;       // 0..255
            int tt = idx >> 2, ch = idx & 3;
            uint32_t doff = tt * 64 + ch * 16;
            size_t gr = grow + tt;
            cp16(s0 + doff,         dtb + gr * DI + d0 + ch * 8);
            cp16(s0 + 4096 + doff,  ub  + gr * DI + d0 + ch * 8);
            cp16(s0 + 8192 + doff,  xzb + gr * XZ_W + DI + d0 + ch * 8);
            // B/C fp32: 64 rows x 16 f32 = 4 cp16/row, 256 per tile
            cp16(s0 + 12288 + doff, xdbl + gr * XDBL_W + DR + ch * 4);
            cp16(s0 + 16384 + doff, xdbl + gr * XDBL_W + DR + DS + ch * 4);
        }
        CP_COMMIT();
    };

    float h0 = 0.f, h1 = 0.f, h2 = 0.f, h3 = 0.f;
    const int nchunks = LL / 64;   // 16

    load_chunk(0, 0);

    for (int c = 0; c < nchunks; ++c) {
        if (c + 1 < nchunks) { load_chunk(c + 1, (c + 1) & 1); CP_WAIT(1); }
        else                 { CP_WAIT(0); }
        __syncthreads();

        const char* Sc = S + (c & 1) * SSTB;
        const __nv_bfloat16* sdt = (const __nv_bfloat16*)Sc;
        const __nv_bfloat16* su  = sdt + 2048;
        const __nv_bfloat16* sz  = su + 2048;
        const float* sB = (const float*)(Sc + 12288);
        const float* sC = (const float*)(Sc + 16384);
        const int t0 = c * 64;

#pragma unroll 4
        for (int tt = 0; tt < 64; ++tt) {
            float dtv = __bfloat162float(sdt[tt * 32 + dl]);
            float uv  = __bfloat162float(su [tt * 32 + dl]);
            float dtu = dtv * uv;

            float dA0 = __expf(dtv * Av[0]);
            float dA1 = __expf(dtv * Av[1]);
            float dA2 = __expf(dtv * Av[2]);
            float dA3 = __expf(dtv * Av[3]);
            h0 = dA0 * h0 + dtu * sB[tt * 16 + q * 4 + 0];
            h1 = dA1 * h1 + dtu * sB[tt * 16 + q * 4 + 1];
            h2 = dA2 * h2 + dtu * sB[tt * 16 + q * 4 + 2];
            h3 = dA3 * h3 + dtu * sB[tt * 16 + q * 4 + 3];
            float ys = h0 * sC[tt * 16 + q * 4 + 0]
                     + h1 * sC[tt * 16 + q * 4 + 1]
                     + h2 * sC[tt * 16 + q * 4 + 2]
                     + h3 * sC[tt * 16 + q * 4 + 3];

            ys += __shfl_xor_sync(0xffffffff, ys, 1);
            ys += __shfl_xor_sync(0xffffffff, ys, 2);

            if (q == 0) {
                float zv = __bfloat162float(sz[tt * 32 + dl]);
                float sz2 = zv / (1.f + __expf(-zv));
                yb[((size_t)b * LL + t0 + tt) * DI + d] =
                    __float2bfloat16((ys + uv * Dv) * sz2);
            }
        }
        __syncthreads();
    }
}

// ---------------- Host launcher ----------------
extern "C" void kernel_launch(void* const* d_in, const int* in_sizes, int n_in,
                              void* d_out, int out_size)
{
    const float* x      = (const float*)d_in[0];
    const float* W_in   = (const float*)d_in[1];
    const float* conv_w = (const float*)d_in[2];
    const float* conv_b = (const float*)d_in[3];
    const float* W_x    = (const float*)d_in[4];
    const float* W_dt   = (const float*)d_in[5];
    const float* b_dt   = (const float*)d_in[6];
    const float* A_log  = (const float*)d_in[7];
    const float* Dvec   = (const float*)d_in[8];
    const float* W_out  = (const float*)d_in[9];
    float* out = (float*)d_out;

    float *xdbl, *xpart;
    __nv_bfloat16 *xzb, *dtb, *xb, *hb, *ub, *yb, *xdblb, *Wib, *Wxb, *Wdtb, *Wob;
    cudaGetSymbolAddress((void**)&xdbl,  g_xdbl);
    cudaGetSymbolAddress((void**)&xpart, g_xpart);
    cudaGetSymbolAddress((void**)&xzb,   g_xzb);
    cudaGetSymbolAddress((void**)&dtb,   g_dtb);
    cudaGetSymbolAddress((void**)&xb,    g_xb);
    cudaGetSymbolAddress((void**)&hb,    g_hb);
    cudaGetSymbolAddress((void**)&ub,    g_ub);
    cudaGetSymbolAddress((void**)&yb,    g_yb);
    cudaGetSymbolAddress((void**)&xdblb, g_xdblb);
    cudaGetSymbolAddress((void**)&Wib,   g_Wib);
    cudaGetSymbolAddress((void**)&Wxb,   g_Wxb);
    cudaGetSymbolAddress((void**)&Wdtb,  g_Wdtb);
    cudaGetSymbolAddress((void**)&Wob,   g_Wob);

    const int SMEM_MI2 = 3 * (128 * 128 + 16384);   // 98304
    const int SMEM_MI1 = 3 * (64 * 128 + 16384);    // 73728
    cudaFuncSetAttribute(gemm_mma<2,3,false>, cudaFuncAttributeMaxDynamicSharedMemorySize, SMEM_MI2);
    cudaFuncSetAttribute(gemm_mma<2,0,true>,  cudaFuncAttributeMaxDynamicSharedMemorySize, SMEM_MI2);
    cudaFuncSetAttribute(gemm_mma<1,1,false>, cudaFuncAttributeMaxDynamicSharedMemorySize, SMEM_MI1);
    cudaFuncSetAttribute(gemm_mma<1,3,false>, cudaFuncAttributeMaxDynamicSharedMemorySize, SMEM_MI1);
    cudaFuncSetAttribute(gemm_mma<1,2,false>, cudaFuncAttributeMaxDynamicSharedMemorySize, SMEM_MI1);
    cudaFuncSetAttribute(scan_kernel, cudaFuncAttributeMaxDynamicSharedMemorySize, SCAN_SMEM);

    // #1: x + W_in -> bf16
    {
        int n1 = MROWS * DM, n2 = 2 * XZ_W * DM;
        cvt2_kernel<<<((n1 + n2) / 8 + 255) / 256, 256>>>(x, xb, n1, W_in, Wib, n2);
    }
    // #2: W_x, W_dt, W_out -> bf16
    {
        int n1 = 2 * XDBL_W * DI, n2 = 2 * DI * DR, n3 = 2 * DM * DI;
        cvt3_kernel<<<((n1 + n2 + n3) / 8 + 255) / 256, 256>>>(
            W_x, Wxb, n1, W_dt, Wdtb, n2, W_out, Wob, n3);
    }

    for (int layer = 0; layer < 2; ++layer) {
        const __nv_bfloat16* in_b   = (layer == 0) ? xb : hb;
        const __nv_bfloat16* Wib_l  = Wib  + (size_t)layer * XZ_W * DM;
        const __nv_bfloat16* Wxb_l  = Wxb  + (size_t)layer * XDBL_W * DI;
        const __nv_bfloat16* Wdtb_l = Wdtb + (size_t)layer * DI * DR;
        const __nv_bfloat16* Wob_l  = Wob  + (size_t)layer * DM * DI;
        const float* conv_w_l = conv_w + (size_t)layer * DI * DC;
        const float* conv_b_l = conv_b + (size_t)layer * DI;
        const float* b_dt_l   = b_dt   + (size_t)layer * DI;
        const float* A_log_l  = A_log  + (size_t)layer * DI * DS;
        const float* D_l      = Dvec   + (size_t)layer * DI;

        // #3: xz(bf16) = in @ W_in^T : M=2048, N=4096, K=1024
        gemm_mma<2,3,false><<<dim3(XZ_W / 128, MROWS / 128), 256, SMEM_MI2>>>(
            in_b, DM, Wib_l, DM, nullptr, xzb, XZ_W, XZ_W, DM, nullptr, nullptr);

        // #4 (profiled, layer 0): u(bf16) = silu(causal_conv(xz[:, :DI]))
        conv_silu_kernel<<<(BB * (LL / 4) * DI) / 256, 256>>>(
            xzb, conv_w_l, conv_b_l, ub);

        // #5: x_dbl partials = u @ W_x^T split-K x8
        gemm_mma<2,0,true><<<dim3(1, MROWS / 128, NSPLIT), 256, SMEM_MI2>>>(
            ub, DI, Wxb_l, DI, xpart, nullptr, XDBL_W, XDBL_W, KSPLIT, nullptr, nullptr);

        // #6: reduce partials -> xdbl fp32 + bf16
        reduce_x_kernel<<<(MROWS * XDBL_W + 255) / 256, 256>>>(xpart, xdbl, xdblb);

        // #7: dt(bf16) = softplus(x_dbl[:, :64] @ W_dt^T + b_dt)
        gemm_mma<1,1,false><<<dim3(DI / 128, MROWS / 64), 256, SMEM_MI1>>>(
            xdblb, XDBL_W, Wdtb_l, DR, nullptr, dtb, DI, DI, DR, b_dt_l, nullptr);

        // #8: selective scan
        scan_kernel<<<BB * (DI / 32), 128, SCAN_SMEM>>>(
            dtb, ub, xdbl, A_log_l, D_l, xzb, yb);

        // #9: out = y @ W_out^T : N=1024, K=2048
        if (layer == 0) {
            gemm_mma<1,3,false><<<dim3(DM / 128, MROWS / 64), 256, SMEM_MI1>>>(
                yb, DI, Wob_l, DI, nullptr, hb, DM, DM, DI, nullptr, nullptr);
        } else {
            gemm_mma<1,2,false><<<dim3(DM / 128, MROWS / 64), 256, SMEM_MI1>>>(
                yb, DI, Wob_l, DI, out, nullptr, DM, DM, DI, nullptr, x);
        }
    }
}